// round 7
// baseline (speedup 1.0000x reference)
#include <cuda_runtime.h>
#include <math.h>

#define BB 2
#define TT 8192
#define HQ 32
#define HH 8
#define DD 64
#define DRR 16
#define NB 128
#define BS 64
#define SELK 16
#define GRP 4
#define TOK_TILE 128

typedef unsigned long long u64;

__device__ float g_Kr[BB * NB * HH * DRR];

// ---------------- Kernel 1: block-mean of K, then project with Wk ----------------
__global__ void kr_kernel(const float* __restrict__ K, const float* __restrict__ Wk) {
    int n = blockIdx.x, h = blockIdx.y, b = blockIdx.z;
    int d = threadIdx.x;  // 64 threads, one per dim
    __shared__ float sm[DD];

    const float* kp = K + ((size_t)((b * TT + n * BS) * HH + h)) * DD + d;
    float acc = 0.f;
#pragma unroll 4
    for (int j = 0; j < BS; ++j) acc += kp[(size_t)j * HH * DD];
    sm[d] = acc * (1.0f / BS);
    __syncthreads();

    if (d < DRR) {
        int r = d;
        const float* wk = Wk + (h * DD) * DRR + r;
        float a = 0.f;
#pragma unroll
        for (int dd = 0; dd < DD; ++dd) a = fmaf(sm[dd], wk[dd * DRR], a);
        g_Kr[((b * NB + n) * HH + h) * DRR + r] = a;
    }
}

// ---------------- Kernel 2: Qr, scores, stable top-16 + locals ----------------
__global__ __launch_bounds__(TOK_TILE) void router_kernel(
    const float* __restrict__ Q, const float* __restrict__ Wq,
    const float* __restrict__ ls, float* __restrict__ out) {
    int tile = blockIdx.x, h = blockIdx.y, b = blockIdx.z;
    int tid = threadIdx.x;

    __shared__ float sWq[DD * DRR];   // 4 KB
    __shared__ float sKr[NB * DRR];   // 8 KB

    for (int i = tid; i < DD * DRR; i += TOK_TILE) sWq[i] = Wq[h * DD * DRR + i];
    for (int i = tid; i < NB * DRR; i += TOK_TILE)
        sKr[i] = g_Kr[((b * NB + (i >> 4)) * HH + h) * DRR + (i & 15)];
    __syncthreads();

    int t = tile * TOK_TILE + tid;
    int tb = t >> 6;  // t_blk
    float scale = expf(ls[h]);

    // Qr = Q-row @ Wq[h]; vectorized float4 loads (row is 16B-aligned)
    const float4* qrow = (const float4*)(Q + ((size_t)((b * TT + t) * HQ + h * GRP)) * DD);
    float Qr[DRR];
#pragma unroll
    for (int r = 0; r < DRR; ++r) Qr[r] = 0.f;
#pragma unroll 4
    for (int d4 = 0; d4 < DD / 4; ++d4) {
        float4 q4 = qrow[d4];
#pragma unroll
        for (int r = 0; r < DRR; ++r) {
            float a = Qr[r];
            a = fmaf(q4.x, sWq[(d4 * 4 + 0) * DRR + r], a);
            a = fmaf(q4.y, sWq[(d4 * 4 + 1) * DRR + r], a);
            a = fmaf(q4.z, sWq[(d4 * 4 + 2) * DRR + r], a);
            a = fmaf(q4.w, sWq[(d4 * 4 + 3) * DRR + r], a);
            Qr[r] = a;
        }
    }

    // ---- stable top-16: causal blocks only (strict >, ascending n = jax tie rule) ----
    const float NEG_INF = __int_as_float(0xff800000);
    float s[16];
    int idx[16];
#pragma unroll
    for (int j = 0; j < 16; ++j) { s[j] = NEG_INF; idx[j] = 10000; }

#pragma unroll 1
    for (int n = 0; n <= tb; ++n) {
        float a = 0.f;
#pragma unroll
        for (int r = 0; r < DRR; ++r) a = fmaf(Qr[r], sKr[n * DRR + r], a);
        float sc = a * scale;
        bool c[16];
#pragma unroll
        for (int j = 0; j < 16; ++j)
            c[j] = (sc > s[j]) || (sc == s[j] && idx[j] == 10000);  // fills empty slots too
#pragma unroll
        for (int j = 15; j >= 1; --j) {
            s[j]   = c[j] ? (c[j - 1] ? s[j - 1]   : sc) : s[j];
            idx[j] = c[j] ? (c[j - 1] ? idx[j - 1] : n ) : idx[j];
        }
        s[0]   = c[0] ? sc : s[0];
        idx[0] = c[0] ? n  : idx[0];
    }
    // masked region: top_k fills remaining slots with -inf ties, lowest index first
    if (tb < 15) {
#pragma unroll 1
        for (int n = tb + 1; n <= 15; ++n) {
            // insert at first empty slot (all finite scores sit above empties)
#pragma unroll
            for (int j = 0; j < 16; ++j)
                if (idx[j] == 10000) { idx[j] = n; break; }
        }
    }

    // ---- selection bitmask (16 distinct block ids < 128) ----
    u64 sel_lo = 0ull, sel_hi = 0ull;
#pragma unroll
    for (int j = 0; j < 16; ++j) {
        int bidx = idx[j];
        if (bidx < 64) sel_lo |= 1ull << bidx;
        else           sel_hi |= 1ull << (bidx - 64);
    }

    // ---- merge ascending bit-walk with 2 local blocks, keep 16 smallest ----
    int l0 = tb;
    int l1 = tb > 0 ? tb - 1 : 0;  // l1 <= l0
    int li = 0;
    int r[16];
#pragma unroll
    for (int k = 0; k < 16; ++k) {
        bool lo_nz = (sel_lo != 0ull);
        int nb = lo_nz ? (__ffsll((long long)sel_lo) - 1)
                       : (64 + __ffsll((long long)sel_hi) - 1);
        int lc = (li == 0) ? l1 : ((li == 1) ? l0 : 0x7FFFFFFF);
        bool tl = (lc <= nb);
        r[k] = tl ? lc : nb;
        li += tl ? 1 : 0;
        if (!tl) {
            if (lo_nz) sel_lo &= (sel_lo - 1ull);
            else       sel_hi &= (sel_hi - 1ull);
        }
    }

    // ---- OUTPUT AS FLOAT32: harness output dtype is float32 (see theory) ----
    float* op = out + ((size_t)((b * TT + t) * HH + h)) * SELK;
    float4* op4 = (float4*)op;
    op4[0] = make_float4((float)r[0],  (float)r[1],  (float)r[2],  (float)r[3]);
    op4[1] = make_float4((float)r[4],  (float)r[5],  (float)r[6],  (float)r[7]);
    op4[2] = make_float4((float)r[8],  (float)r[9],  (float)r[10], (float)r[11]);
    op4[3] = make_float4((float)r[12], (float)r[13], (float)r[14], (float)r[15]);
}

// ---------------- launch: identify inputs by element count, not position ----------------
extern "C" void kernel_launch(void* const* d_in, const int* in_sizes, int n_in,
                              void* d_out, int out_size) {
    const long long SZ_Q  = (long long)BB * TT * HQ * DD;  // 33554432
    const long long SZ_K  = (long long)BB * TT * HH * DD;  // 8388608
    const long long SZ_W  = HH * DD * DRR;                 // 8192
    const long long SZ_LS = HH;                            // 8

    // Detect units: if any size equals Q's BYTE count, sizes are bytes.
    long long unit = 1;
    for (int i = 0; i < n_in; ++i)
        if ((long long)in_sizes[i] == SZ_Q * 4) unit = 4;

    int iQ = -1, iK = -1, iW1 = -1, iW2 = -1, iLS = -1;
    for (int i = 0; i < n_in; ++i) {
        long long s = (long long)in_sizes[i];
        if (s == SZ_Q * unit) iQ = i;
        else if (s == SZ_K * unit) iK = i;
        else if (s == SZ_W * unit) { if (iW1 < 0) iW1 = i; else iW2 = i; }
        else if (s == SZ_LS * unit) iLS = i;
    }
    // Q-before-K  <=>  insertion order  <=>  first W-array is Wq
    int iWq = (iQ >= 0 && iK >= 0 && iQ < iK) ? iW1 : iW2;
    int iWk = (iQ >= 0 && iK >= 0 && iQ < iK) ? iW2 : iW1;
    if (iQ < 0) iQ = 0;
    if (iK < 0) iK = 1;
    if (iWq < 0) iWq = 2;
    if (iWk < 0) iWk = 3;
    if (iLS < 0) iLS = 4;

    const float* Q  = (const float*)d_in[iQ];
    const float* K  = (const float*)d_in[iK];
    const float* Wq = (const float*)d_in[iWq];
    const float* Wk = (const float*)d_in[iWk];
    const float* ls = (const float*)d_in[iLS];
    float* out = (float*)d_out;

    dim3 g1(NB, HH, BB);
    kr_kernel<<<g1, 64>>>(K, Wk);

    dim3 g2(TT / TOK_TILE, HH, BB);
    router_kernel<<<g2, TOK_TILE>>>(Q, Wq, ls, out);
}

// round 8
// speedup vs baseline: 2.0408x; 2.0408x over previous
#include <cuda_runtime.h>
#include <math.h>

#define BB 2
#define TT 8192
#define HQ 32
#define HH 8
#define DD 64
#define DRR 16
#define NB 128
#define BS 64
#define SELK 16
#define GRP 4
#define TOK_TILE 128

typedef unsigned long long u64;

__device__ float g_Kr[BB * NB * HH * DRR];

// ---------------- Kernel 1: block-mean of K, then project with Wk (unchanged) ----------------
__global__ void kr_kernel(const float* __restrict__ K, const float* __restrict__ Wk) {
    int n = blockIdx.x, h = blockIdx.y, b = blockIdx.z;
    int d = threadIdx.x;  // 64 threads, one per dim
    __shared__ float sm[DD];

    const float* kp = K + ((size_t)((b * TT + n * BS) * HH + h)) * DD + d;
    float acc = 0.f;
#pragma unroll 4
    for (int j = 0; j < BS; ++j) acc += kp[(size_t)j * HH * DD];
    sm[d] = acc * (1.0f / BS);
    __syncthreads();

    if (d < DRR) {
        int r = d;
        const float* wk = Wk + (h * DD) * DRR + r;
        float a = 0.f;
#pragma unroll
        for (int dd = 0; dd < DD; ++dd) a = fmaf(sm[dd], wk[dd * DRR], a);
        g_Kr[((b * NB + n) * HH + h) * DRR + r] = a;
    }
}

// ---------------- sorting-network helpers (values only; ties irrelevant for tau) ----------------
__device__ __forceinline__ void ce_asc(float& a, float& b) {
    float mn = fminf(a, b), mx = fmaxf(a, b);
    a = mn; b = mx;
}
// full bitonic sort, ascending, 16 elements (80 compare-exchanges)
__device__ __forceinline__ void sort16_asc(float (&v)[16]) {
#pragma unroll
    for (int k = 2; k <= 16; k <<= 1) {
#pragma unroll
        for (int j = k >> 1; j > 0; j >>= 1) {
#pragma unroll
            for (int i = 0; i < 16; ++i) {
                int l = i ^ j;
                if (l > i) {
                    if ((i & k) == 0) ce_asc(v[i], v[l]);
                    else              ce_asc(v[l], v[i]);
                }
            }
        }
    }
}
// ascending clean of a bitonic 16-seq (32 compare-exchanges)
__device__ __forceinline__ void bitonic_clean16_asc(float (&v)[16]) {
#pragma unroll
    for (int j = 8; j > 0; j >>= 1) {
#pragma unroll
        for (int i = 0; i < 16; ++i) {
            if ((i & j) == 0) ce_asc(v[i], v[i | j]);
        }
    }
}

// Score: EXACT accumulation order of the passing R6 kernel (serial fmaf, r ascending).
// float4 loads change nothing numerically. Used in both passes -> identical bits.
__device__ __forceinline__ float score16(const float4* __restrict__ sKr4,
                                         const float* __restrict__ Qr,
                                         int n, float scale) {
    float4 k0 = sKr4[n * 4 + 0];
    float4 k1 = sKr4[n * 4 + 1];
    float4 k2 = sKr4[n * 4 + 2];
    float4 k3 = sKr4[n * 4 + 3];
    float a = 0.f;
    a = fmaf(Qr[0],  k0.x, a); a = fmaf(Qr[1],  k0.y, a);
    a = fmaf(Qr[2],  k0.z, a); a = fmaf(Qr[3],  k0.w, a);
    a = fmaf(Qr[4],  k1.x, a); a = fmaf(Qr[5],  k1.y, a);
    a = fmaf(Qr[6],  k1.z, a); a = fmaf(Qr[7],  k1.w, a);
    a = fmaf(Qr[8],  k2.x, a); a = fmaf(Qr[9],  k2.y, a);
    a = fmaf(Qr[10], k2.z, a); a = fmaf(Qr[11], k2.w, a);
    a = fmaf(Qr[12], k3.x, a); a = fmaf(Qr[13], k3.y, a);
    a = fmaf(Qr[14], k3.z, a); a = fmaf(Qr[15], k3.w, a);
    return a * scale;
}

// ---------------- Kernel 2: Qr, tau via sorting network, bitmask select ----------------
__global__ __launch_bounds__(TOK_TILE) void router_kernel(
    const float* __restrict__ Q, const float* __restrict__ Wq,
    const float* __restrict__ ls, float* __restrict__ out) {
    int tile = blockIdx.x, h = blockIdx.y, b = blockIdx.z;
    int tid = threadIdx.x;

    __shared__ __align__(16) float sWq[DD * DRR];   // 4 KB
    __shared__ __align__(16) float sKr[NB * DRR];   // 8 KB

    for (int i = tid; i < DD * DRR; i += TOK_TILE) sWq[i] = Wq[h * DD * DRR + i];
    for (int i = tid; i < NB * DRR; i += TOK_TILE)
        sKr[i] = g_Kr[((b * NB + (i >> 4)) * HH + h) * DRR + (i & 15)];
    __syncthreads();

    int t = tile * TOK_TILE + tid;
    int tb = t >> 6;  // t_blk
    float scale = expf(ls[h]);

    // Qr = Q-row @ Wq[h] — numerics verbatim from the passing kernel
    const float4* qrow = (const float4*)(Q + ((size_t)((b * TT + t) * HQ + h * GRP)) * DD);
    float Qr[DRR];
#pragma unroll
    for (int r = 0; r < DRR; ++r) Qr[r] = 0.f;
#pragma unroll 4
    for (int d4 = 0; d4 < DD / 4; ++d4) {
        float4 q4 = qrow[d4];
#pragma unroll
        for (int r = 0; r < DRR; ++r) {
            float a = Qr[r];
            a = fmaf(q4.x, sWq[(d4 * 4 + 0) * DRR + r], a);
            a = fmaf(q4.y, sWq[(d4 * 4 + 1) * DRR + r], a);
            a = fmaf(q4.z, sWq[(d4 * 4 + 2) * DRR + r], a);
            a = fmaf(q4.w, sWq[(d4 * 4 + 3) * DRR + r], a);
            Qr[r] = a;
        }
    }

    const float4* sKr4 = (const float4*)sKr;
    const float NEG_INF = __int_as_float(0xff800000);

    // ---- pass 1: tau = 16th-largest score, via batched bitonic top-16 ----
    float s[16];
#pragma unroll
    for (int j = 0; j < 16; ++j) s[j] = NEG_INF;   // ascending top-16 (s[0] = 16th largest)

#pragma unroll 1
    for (int base = 0; base <= tb; base += 16) {
        float Bv[16];
#pragma unroll
        for (int i = 0; i < 16; ++i) {
            int n = base + i;
            float sc = score16(sKr4, Qr, n, scale);   // sKr valid for all n<128
            Bv[i] = (n <= tb) ? sc : NEG_INF;
        }
        sort16_asc(Bv);
        // half-cleaner: keep the 16 largest of s ∪ Bv (elementwise, no cross-dep)
#pragma unroll
        for (int i = 0; i < 16; ++i) s[i] = fmaxf(s[i], Bv[15 - i]);
        bitonic_clean16_asc(s);                      // s bitonic -> ascending
    }
    float tau = (tb >= 15) ? s[0] : -1e30f;

    // ---- pass 2: >tau / ==tau bitmasks; recompute is bitwise-identical ----
    u64 gt_lo = 0, eq_lo = 0, gt_hi = 0, eq_hi = 0;
    int nlo = tb < 63 ? tb : 63;
#pragma unroll 2
    for (int n = 0; n <= nlo; ++n) {
        float sc = score16(sKr4, Qr, n, scale);
        u64 bit = 1ull << n;
        if (sc > tau) gt_lo |= bit;
        else if (sc == tau) eq_lo |= bit;
    }
#pragma unroll 2
    for (int n = 64; n <= tb; ++n) {
        float sc = score16(sKr4, Qr, n, scale);
        u64 bit = 1ull << (n - 64);
        if (sc > tau) gt_hi |= bit;
        else if (sc == tau) eq_hi |= bit;
    }
    if (tb < 15) {
        gt_lo |= ((1ull << 15) - (2ull << tb));  // surrogate blocks tb+1..14 (masked, > tau)
        eq_lo |= (1ull << 15);                   // surrogate block 15 (tie)
    }

    // tie-fill: lowest-index ==tau bits until 16 selected (jax stable tie rule)
    int need = 16 - __popcll(gt_lo) - __popcll(gt_hi);
    u64 sel_lo = gt_lo, sel_hi = gt_hi;
#pragma unroll 1
    for (int it = 0; it < 16 && need > 0; ++it) {
        if (eq_lo) { u64 bb = eq_lo & (0ull - eq_lo); sel_lo |= bb; eq_lo ^= bb; }
        else if (eq_hi) { u64 bb = eq_hi & (0ull - eq_hi); sel_hi |= bb; eq_hi ^= bb; }
        --need;
    }

    // ---- emit: merge ascending bit-walk with 2 local blocks, keep 16 smallest ----
    int l0 = tb;
    int l1 = tb > 0 ? tb - 1 : 0;  // l1 <= l0
    int li = 0;
    int r[16];
#pragma unroll
    for (int k = 0; k < 16; ++k) {
        bool lo_nz = (sel_lo != 0ull);
        int nb = lo_nz ? (__ffsll((long long)sel_lo) - 1)
                       : (64 + __ffsll((long long)sel_hi) - 1);
        int lc = (li == 0) ? l1 : ((li == 1) ? l0 : 0x7FFFFFFF);
        bool tl = (lc <= nb);
        r[k] = tl ? lc : nb;
        li += tl ? 1 : 0;
        if (!tl) {
            if (lo_nz) sel_lo &= (sel_lo - 1ull);
            else       sel_hi &= (sel_hi - 1ull);
        }
    }

    // output dtype is float32 (R7 finding)
    float* op = out + ((size_t)((b * TT + t) * HH + h)) * SELK;
    float4* op4 = (float4*)op;
    op4[0] = make_float4((float)r[0],  (float)r[1],  (float)r[2],  (float)r[3]);
    op4[1] = make_float4((float)r[4],  (float)r[5],  (float)r[6],  (float)r[7]);
    op4[2] = make_float4((float)r[8],  (float)r[9],  (float)r[10], (float)r[11]);
    op4[3] = make_float4((float)r[12], (float)r[13], (float)r[14], (float)r[15]);
}

// ---------------- launch: identify inputs by element count (unchanged, passing) ----------------
extern "C" void kernel_launch(void* const* d_in, const int* in_sizes, int n_in,
                              void* d_out, int out_size) {
    const long long SZ_Q  = (long long)BB * TT * HQ * DD;  // 33554432
    const long long SZ_K  = (long long)BB * TT * HH * DD;  // 8388608
    const long long SZ_W  = HH * DD * DRR;                 // 8192
    const long long SZ_LS = HH;                            // 8

    long long unit = 1;
    for (int i = 0; i < n_in; ++i)
        if ((long long)in_sizes[i] == SZ_Q * 4) unit = 4;

    int iQ = -1, iK = -1, iW1 = -1, iW2 = -1, iLS = -1;
    for (int i = 0; i < n_in; ++i) {
        long long s = (long long)in_sizes[i];
        if (s == SZ_Q * unit) iQ = i;
        else if (s == SZ_K * unit) iK = i;
        else if (s == SZ_W * unit) { if (iW1 < 0) iW1 = i; else iW2 = i; }
        else if (s == SZ_LS * unit) iLS = i;
    }
    int iWq = (iQ >= 0 && iK >= 0 && iQ < iK) ? iW1 : iW2;
    int iWk = (iQ >= 0 && iK >= 0 && iQ < iK) ? iW2 : iW1;
    if (iQ < 0) iQ = 0;
    if (iK < 0) iK = 1;
    if (iWq < 0) iWq = 2;
    if (iWk < 0) iWk = 3;
    if (iLS < 0) iLS = 4;

    const float* Q  = (const float*)d_in[iQ];
    const float* K  = (const float*)d_in[iK];
    const float* Wq = (const float*)d_in[iWq];
    const float* Wk = (const float*)d_in[iWk];
    const float* ls = (const float*)d_in[iLS];
    float* out = (float*)d_out;

    dim3 g1(NB, HH, BB);
    kr_kernel<<<g1, 64>>>(K, Wk);

    dim3 g2(TT / TOK_TILE, HH, BB);
    router_kernel<<<g2, TOK_TILE>>>(Q, Wq, ls, out);
}

// round 12
// speedup vs baseline: 2.0887x; 1.0234x over previous
#include <cuda_runtime.h>
#include <math.h>

#define BB 2
#define TT 8192
#define HQ 32
#define HH 8
#define DD 64
#define DRR 16
#define NB 128
#define BS 64
#define SELK 16
#define GRP 4
#define TOK_TILE 128

typedef unsigned long long u64;

__device__ float g_Kr[BB * NB * HH * DRR];

// ---------------- Kernel 1: block-mean of K, then project with Wk (unchanged) ----------------
__global__ void kr_kernel(const float* __restrict__ K, const float* __restrict__ Wk) {
    int n = blockIdx.x, h = blockIdx.y, b = blockIdx.z;
    int d = threadIdx.x;  // 64 threads, one per dim
    __shared__ float sm[DD];

    const float* kp = K + ((size_t)((b * TT + n * BS) * HH + h)) * DD + d;
    float acc = 0.f;
#pragma unroll 4
    for (int j = 0; j < BS; ++j) acc += kp[(size_t)j * HH * DD];
    sm[d] = acc * (1.0f / BS);
    __syncthreads();

    if (d < DRR) {
        int r = d;
        const float* wk = Wk + (h * DD) * DRR + r;
        float a = 0.f;
#pragma unroll
        for (int dd = 0; dd < DD; ++dd) a = fmaf(sm[dd], wk[dd * DRR], a);
        g_Kr[((b * NB + n) * HH + h) * DRR + r] = a;
    }
}

// ---------------- f32x2 helpers (each lane rounds exactly like scalar fmaf) ----------------
__device__ __forceinline__ u64 ffma2(u64 a, u64 b, u64 c) {
    u64 d;
    asm("fma.rn.f32x2 %0, %1, %2, %3;" : "=l"(d) : "l"(a), "l"(b), "l"(c));
    return d;
}
__device__ __forceinline__ u64 pack2(float x, float y) {
    u64 r;
    asm("mov.b64 %0, {%1, %2};" : "=l"(r) : "f"(x), "f"(y));
    return r;
}
__device__ __forceinline__ void unpack2(u64 v, float& x, float& y) {
    asm("mov.b64 {%0, %1}, %2;" : "=f"(x), "=f"(y) : "l"(v));
}

// ---------------- sorting-network helpers (values only) ----------------
__device__ __forceinline__ void ce_asc(float& a, float& b) {
    float mn = fminf(a, b), mx = fmaxf(a, b);
    a = mn; b = mx;
}
__device__ __forceinline__ void sort16_asc(float (&v)[16]) {
#pragma unroll
    for (int k = 2; k <= 16; k <<= 1) {
#pragma unroll
        for (int j = k >> 1; j > 0; j >>= 1) {
#pragma unroll
            for (int i = 0; i < 16; ++i) {
                int l = i ^ j;
                if (l > i) {
                    if ((i & k) == 0) ce_asc(v[i], v[l]);
                    else              ce_asc(v[l], v[i]);
                }
            }
        }
    }
}
__device__ __forceinline__ void bitonic_clean16_asc(float (&v)[16]) {
#pragma unroll
    for (int j = 8; j > 0; j >>= 1) {
#pragma unroll
        for (int i = 0; i < 16; ++i) {
            if ((i & j) == 0) ce_asc(v[i], v[i | j]);
        }
    }
}

// Score: EXACT serial-fmaf accumulation order (frozen numerics; both passes identical).
__device__ __forceinline__ float score16(const float4* __restrict__ sKr4,
                                         const float* __restrict__ Qr,
                                         int n, float scale) {
    float4 k0 = sKr4[n * 4 + 0];
    float4 k1 = sKr4[n * 4 + 1];
    float4 k2 = sKr4[n * 4 + 2];
    float4 k3 = sKr4[n * 4 + 3];
    float a = 0.f;
    a = fmaf(Qr[0],  k0.x, a); a = fmaf(Qr[1],  k0.y, a);
    a = fmaf(Qr[2],  k0.z, a); a = fmaf(Qr[3],  k0.w, a);
    a = fmaf(Qr[4],  k1.x, a); a = fmaf(Qr[5],  k1.y, a);
    a = fmaf(Qr[6],  k1.z, a); a = fmaf(Qr[7],  k1.w, a);
    a = fmaf(Qr[8],  k2.x, a); a = fmaf(Qr[9],  k2.y, a);
    a = fmaf(Qr[10], k2.z, a); a = fmaf(Qr[11], k2.w, a);
    a = fmaf(Qr[12], k3.x, a); a = fmaf(Qr[13], k3.y, a);
    a = fmaf(Qr[14], k3.z, a); a = fmaf(Qr[15], k3.w, a);
    return a * scale;
}

// ---------------- Kernel 2: Qr (f32x2), tau via sorting network, bitmask select ----------------
__global__ __launch_bounds__(TOK_TILE, 8) void router_kernel(
    const float* __restrict__ Q, const float* __restrict__ Wq,
    const float* __restrict__ ls, float* __restrict__ out) {
    int tile = blockIdx.x, h = blockIdx.y, b = blockIdx.z;
    int tid = threadIdx.x;

    __shared__ __align__(16) float sWq[DD * DRR];   // 4 KB, [d][r]
    __shared__ __align__(16) float sKr[NB * DRR];   // 8 KB, [n][r]

    for (int i = tid; i < DD * DRR; i += TOK_TILE) sWq[i] = Wq[h * DD * DRR + i];
    for (int i = tid; i < NB * DRR; i += TOK_TILE)
        sKr[i] = g_Kr[((b * NB + (i >> 4)) * HH + h) * DRR + (i & 15)];
    __syncthreads();

    int t = tile * TOK_TILE + tid;
    int tb = t >> 6;  // t_blk
    float scale = expf(ls[h]);

    // Qr = Q-row @ Wq[h] — f32x2-packed, BIT-EXACT vs scalar (independent r-chains,
    // same d order, each f32x2 lane rounds like fmaf).
    const float4* qrow = (const float4*)(Q + ((size_t)((b * TT + t) * HQ + h * GRP)) * DD);
    u64 QR2[8];
#pragma unroll
    for (int r2 = 0; r2 < 8; ++r2) QR2[r2] = 0ull;
#pragma unroll 4
    for (int d4 = 0; d4 < DD / 4; ++d4) {
        float4 q4 = qrow[d4];
        float qv[4] = {q4.x, q4.y, q4.z, q4.w};
#pragma unroll
        for (int sub = 0; sub < 4; ++sub) {
            u64 qq = pack2(qv[sub], qv[sub]);
            const ulonglong2* wrow = (const ulonglong2*)&sWq[(d4 * 4 + sub) * DRR];
#pragma unroll
            for (int k = 0; k < 4; ++k) {      // 4x LDS.128 = 8 r-pairs
                ulonglong2 w2 = wrow[k];
                QR2[2 * k]     = ffma2(qq, w2.x, QR2[2 * k]);
                QR2[2 * k + 1] = ffma2(qq, w2.y, QR2[2 * k + 1]);
            }
        }
    }
    float Qr[DRR];
#pragma unroll
    for (int r2 = 0; r2 < 8; ++r2) unpack2(QR2[r2], Qr[2 * r2], Qr[2 * r2 + 1]);

    const float4* sKr4 = (const float4*)sKr;
    const float NEG_INF = __int_as_float(0xff800000);

    // ---- pass 1: tau = 16th-largest score, batched bitonic top-16 ----
    float s[16];
#pragma unroll
    for (int j = 0; j < 16; ++j) s[j] = NEG_INF;   // ascending (s[0] = 16th largest)

#pragma unroll 1
    for (int base = 0; base <= tb; base += 16) {
        float Bv[16];
#pragma unroll
        for (int i = 0; i < 16; ++i) {
            int n = base + i;
            float sc = score16(sKr4, Qr, n, scale);
            Bv[i] = (n <= tb) ? sc : NEG_INF;
        }
        sort16_asc(Bv);
#pragma unroll
        for (int i = 0; i < 16; ++i) s[i] = fmaxf(s[i], Bv[15 - i]);
        bitonic_clean16_asc(s);
    }
    float tau = (tb >= 15) ? s[0] : -1e30f;

    // ---- pass 2: >tau / ==tau bitmasks (x4 unroll for ILP); identical score bits ----
    u64 gt_lo = 0, eq_lo = 0, gt_hi = 0, eq_hi = 0;
    int nlo = tb < 63 ? tb : 63;
#pragma unroll 4
    for (int n = 0; n <= nlo; ++n) {
        float sc = score16(sKr4, Qr, n, scale);
        u64 bit = 1ull << n;
        if (sc > tau) gt_lo |= bit;
        else if (sc == tau) eq_lo |= bit;
    }
#pragma unroll 4
    for (int n = 64; n <= tb; ++n) {
        float sc = score16(sKr4, Qr, n, scale);
        u64 bit = 1ull << (n - 64);
        if (sc > tau) gt_hi |= bit;
        else if (sc == tau) eq_hi |= bit;
    }
    if (tb < 15) {
        gt_lo |= ((1ull << 15) - (2ull << tb));  // surrogate masked blocks tb+1..14 (> tau)
        eq_lo |= (1ull << 15);                   // surrogate block 15 (tie)
    }

    // tie-fill: lowest-index ==tau bits until 16 selected (jax stable tie rule)
    int need = 16 - __popcll(gt_lo) - __popcll(gt_hi);
    u64 sel_lo = gt_lo, sel_hi = gt_hi;
#pragma unroll 1
    for (int it = 0; it < 16 && need > 0; ++it) {
        if (eq_lo) { u64 bb = eq_lo & (0ull - eq_lo); sel_lo |= bb; eq_lo ^= bb; }
        else if (eq_hi) { u64 bb = eq_hi & (0ull - eq_hi); sel_hi |= bb; eq_hi ^= bb; }
        --need;
    }

    // ---- emit: merge ascending bit-walk with 2 local blocks, keep 16 smallest ----
    int l0 = tb;
    int l1 = tb > 0 ? tb - 1 : 0;  // l1 <= l0
    int li = 0;
    int r[16];
#pragma unroll
    for (int k = 0; k < 16; ++k) {
        bool lo_nz = (sel_lo != 0ull);
        int nb = lo_nz ? (__ffsll((long long)sel_lo) - 1)
                       : (64 + __ffsll((long long)sel_hi) - 1);
        int lc = (li == 0) ? l1 : ((li == 1) ? l0 : 0x7FFFFFFF);
        bool tl = (lc <= nb);
        r[k] = tl ? lc : nb;
        li += tl ? 1 : 0;
        if (!tl) {
            if (lo_nz) sel_lo &= (sel_lo - 1ull);
            else       sel_hi &= (sel_hi - 1ull);
        }
    }

    // output dtype is float32 (R7 finding)
    float* op = out + ((size_t)((b * TT + t) * HH + h)) * SELK;
    float4* op4 = (float4*)op;
    op4[0] = make_float4((float)r[0],  (float)r[1],  (float)r[2],  (float)r[3]);
    op4[1] = make_float4((float)r[4],  (float)r[5],  (float)r[6],  (float)r[7]);
    op4[2] = make_float4((float)r[8],  (float)r[9],  (float)r[10], (float)r[11]);
    op4[3] = make_float4((float)r[12], (float)r[13], (float)r[14], (float)r[15]);
}

// ---------------- launch: identify inputs by element count (unchanged, passing) ----------------
extern "C" void kernel_launch(void* const* d_in, const int* in_sizes, int n_in,
                              void* d_out, int out_size) {
    const long long SZ_Q  = (long long)BB * TT * HQ * DD;  // 33554432
    const long long SZ_K  = (long long)BB * TT * HH * DD;  // 8388608
    const long long SZ_W  = HH * DD * DRR;                 // 8192
    const long long SZ_LS = HH;                            // 8

    long long unit = 1;
    for (int i = 0; i < n_in; ++i)
        if ((long long)in_sizes[i] == SZ_Q * 4) unit = 4;

    int iQ = -1, iK = -1, iW1 = -1, iW2 = -1, iLS = -1;
    for (int i = 0; i < n_in; ++i) {
        long long s = (long long)in_sizes[i];
        if (s == SZ_Q * unit) iQ = i;
        else if (s == SZ_K * unit) iK = i;
        else if (s == SZ_W * unit) { if (iW1 < 0) iW1 = i; else iW2 = i; }
        else if (s == SZ_LS * unit) iLS = i;
    }
    int iWq = (iQ >= 0 && iK >= 0 && iQ < iK) ? iW1 : iW2;
    int iWk = (iQ >= 0 && iK >= 0 && iQ < iK) ? iW2 : iW1;
    if (iQ < 0) iQ = 0;
    if (iK < 0) iK = 1;
    if (iWq < 0) iWq = 2;
    if (iWk < 0) iWk = 3;
    if (iLS < 0) iLS = 4;

    const float* Q  = (const float*)d_in[iQ];
    const float* K  = (const float*)d_in[iK];
    const float* Wq = (const float*)d_in[iWq];
    const float* Wk = (const float*)d_in[iWk];
    const float* ls = (const float*)d_in[iLS];
    float* out = (float*)d_out;

    dim3 g1(NB, HH, BB);
    kr_kernel<<<g1, 64>>>(K, Wk);

    dim3 g2(TT / TOK_TILE, HH, BB);
    router_kernel<<<g2, TOK_TILE>>>(Q, Wq, ls, out);
}

// round 14
// speedup vs baseline: 2.4303x; 1.1635x over previous
#include <cuda_runtime.h>
#include <math.h>

#define BB 2
#define TT 8192
#define HQ 32
#define HH 8
#define DD 64
#define DRR 16
#define NB 128
#define BS 64
#define SELK 16
#define GRP 4
#define TOK_TILE 128
#define TPAD 132   // padded row stride of transposed Kr (conflict-free)

typedef unsigned long long u64;

__device__ float g_Kr[BB * NB * HH * DRR];

// ---------------- Kernel 1: block-mean of K, then project with Wk (unchanged) ----------------
__global__ void kr_kernel(const float* __restrict__ K, const float* __restrict__ Wk) {
    int n = blockIdx.x, h = blockIdx.y, b = blockIdx.z;
    int d = threadIdx.x;  // 64 threads, one per dim
    __shared__ float sm[DD];

    const float* kp = K + ((size_t)((b * TT + n * BS) * HH + h)) * DD + d;
    float acc = 0.f;
#pragma unroll 4
    for (int j = 0; j < BS; ++j) acc += kp[(size_t)j * HH * DD];
    sm[d] = acc * (1.0f / BS);
    __syncthreads();

    if (d < DRR) {
        int r = d;
        const float* wk = Wk + (h * DD) * DRR + r;
        float a = 0.f;
#pragma unroll
        for (int dd = 0; dd < DD; ++dd) a = fmaf(sm[dd], wk[dd * DRR], a);
        g_Kr[((b * NB + n) * HH + h) * DRR + r] = a;
    }
}

// ---------------- f32x2 helpers (each lane rounds exactly like the scalar op) ----------------
__device__ __forceinline__ u64 ffma2(u64 a, u64 b, u64 c) {
    u64 d;
    asm("fma.rn.f32x2 %0, %1, %2, %3;" : "=l"(d) : "l"(a), "l"(b), "l"(c));
    return d;
}
__device__ __forceinline__ u64 fmul2(u64 a, u64 b) {
    u64 d;
    asm("mul.rn.f32x2 %0, %1, %2;" : "=l"(d) : "l"(a), "l"(b));
    return d;
}
__device__ __forceinline__ u64 pack2(float x, float y) {
    u64 r;
    asm("mov.b64 %0, {%1, %2};" : "=l"(r) : "f"(x), "f"(y));
    return r;
}
__device__ __forceinline__ void unpack2(u64 v, float& x, float& y) {
    asm("mov.b64 {%0, %1}, %2;" : "=f"(x), "=f"(y) : "l"(v));
}

// ---------------- sorting-network helpers (values only) ----------------
__device__ __forceinline__ void ce_asc(float& a, float& b) {
    float mn = fminf(a, b), mx = fmaxf(a, b);
    a = mn; b = mx;
}
__device__ __forceinline__ void sort16_asc(float (&v)[16]) {
#pragma unroll
    for (int k = 2; k <= 16; k <<= 1) {
#pragma unroll
        for (int j = k >> 1; j > 0; j >>= 1) {
#pragma unroll
            for (int i = 0; i < 16; ++i) {
                int l = i ^ j;
                if (l > i) {
                    if ((i & k) == 0) ce_asc(v[i], v[l]);
                    else              ce_asc(v[l], v[i]);
                }
            }
        }
    }
}
__device__ __forceinline__ void bitonic_clean16_asc(float (&v)[16]) {
#pragma unroll
    for (int j = 8; j > 0; j >>= 1) {
#pragma unroll
        for (int i = 0; i < 16; ++i) {
            if ((i & j) == 0) ce_asc(v[i], v[i | j]);
        }
    }
}

// ---------------- Kernel 2: balanced chunks + f32x2 transposed scoring ----------------
__global__ __launch_bounds__(TOK_TILE, 7) void router_kernel(
    const float* __restrict__ Q, const float* __restrict__ Wq,
    const float* __restrict__ ls, float* __restrict__ out) {
    int k = blockIdx.x;          // 0..63
    int h = blockIdx.y, b = blockIdx.z;
    int tid = threadIdx.x, warp = tid >> 5, lane = tid & 31;

    __shared__ __align__(16) float sWq[DD * DRR];    // 4 KB  [d][r]
    __shared__ __align__(16) float sKrT[DRR * TPAD]; // 8.25 KB transposed [r][n]

    for (int i = tid; i < DD * DRR; i += TOK_TILE) sWq[i] = Wq[h * DD * DRR + i];
    for (int i = tid; i < NB * DRR; i += TOK_TILE) {
        int n = i >> 4, r = i & 15;  // coalesced read, padded transpose write
        sKrT[r * TPAD + n] = g_Kr[((b * NB + n) * HH + h) * DRR + r];
    }
    __syncthreads();

    // balanced chunk assignment: per (b,h), CTA k handles chunks {k, 64+k, 191-k, 255-k}
    // -> constant total work per CTA (sum of tb == 254 for every k); tb warp-uniform.
    int c = (warp == 0) ? k : (warp == 1) ? (64 + k) : (warp == 2) ? (191 - k) : (255 - k);
    int t = c * 32 + lane;
    int tb = c >> 1;  // == t >> 6 (chunk spans half a 64-token block)
    float scale = expf(ls[h]);

    // Qr = Q-row @ Wq[h] — f32x2-packed, bit-exact vs scalar (unchanged from R12)
    const float4* qrow = (const float4*)(Q + ((size_t)((b * TT + t) * HQ + h * GRP)) * DD);
    u64 QR2[8];
#pragma unroll
    for (int r2 = 0; r2 < 8; ++r2) QR2[r2] = 0ull;
#pragma unroll 4
    for (int d4 = 0; d4 < DD / 4; ++d4) {
        float4 q4 = qrow[d4];
        float qv[4] = {q4.x, q4.y, q4.z, q4.w};
#pragma unroll
        for (int sub = 0; sub < 4; ++sub) {
            u64 qq = pack2(qv[sub], qv[sub]);
            const ulonglong2* wrow = (const ulonglong2*)&sWq[(d4 * 4 + sub) * DRR];
#pragma unroll
            for (int kk = 0; kk < 4; ++kk) {
                ulonglong2 w2 = wrow[kk];
                QR2[2 * kk]     = ffma2(qq, w2.x, QR2[2 * kk]);
                QR2[2 * kk + 1] = ffma2(qq, w2.y, QR2[2 * kk + 1]);
            }
        }
    }
    // broadcast-packed Qr for the score engine (lane0 == lane1 == Qr[r])
    u64 qr2[DRR];
#pragma unroll
    for (int r2 = 0; r2 < 8; ++r2) {
        float x, y;
        unpack2(QR2[r2], x, y);
        qr2[2 * r2]     = pack2(x, x);
        qr2[2 * r2 + 1] = pack2(y, y);
    }
    u64 scale2 = pack2(scale, scale);

    const float NEG_INF = __int_as_float(0xff800000);

    // ---- pass 1: tau = 16th-largest score; 16 scores as 8 packed chains per batch ----
    float s[16];
#pragma unroll
    for (int j = 0; j < 16; ++j) s[j] = NEG_INF;  // ascending (s[0] = 16th largest)

    int nbatch = (tb >> 4) + 1;  // warp-uniform
#pragma unroll 1
    for (int bt = 0; bt < nbatch; ++bt) {
        int base = bt * 16;
        u64 acc2[8];
#pragma unroll
        for (int j = 0; j < 8; ++j) acc2[j] = 0ull;
#pragma unroll
        for (int r = 0; r < DRR; ++r) {
            const ulonglong2* p = (const ulonglong2*)&sKrT[r * TPAD + base];
            ulonglong2 p0 = p[0], p1 = p[1], p2 = p[2], p3 = p[3];
            u64 q = qr2[r];
            acc2[0] = ffma2(q, p0.x, acc2[0]); acc2[1] = ffma2(q, p0.y, acc2[1]);
            acc2[2] = ffma2(q, p1.x, acc2[2]); acc2[3] = ffma2(q, p1.y, acc2[3]);
            acc2[4] = ffma2(q, p2.x, acc2[4]); acc2[5] = ffma2(q, p2.y, acc2[5]);
            acc2[6] = ffma2(q, p3.x, acc2[6]); acc2[7] = ffma2(q, p3.y, acc2[7]);
        }
        float Bv[16];
#pragma unroll
        for (int j = 0; j < 8; ++j) {
            u64 m = fmul2(acc2[j], scale2);
            unpack2(m, Bv[2 * j], Bv[2 * j + 1]);
        }
        if (bt == nbatch - 1) {          // warp-uniform tail mask
            int lim = tb - base;         // 0..15
#pragma unroll
            for (int i = 0; i < 16; ++i) Bv[i] = (i <= lim) ? Bv[i] : NEG_INF;
        }
        sort16_asc(Bv);
#pragma unroll
        for (int i = 0; i < 16; ++i) s[i] = fmaxf(s[i], Bv[15 - i]);
        bitonic_clean16_asc(s);
    }
    float tau = (tb >= 15) ? s[0] : -1e30f;

    // ---- pass 2: >tau / ==tau bitmasks; 4 scores per group, 2 packed chains ----
    u64 gt_lo = 0, eq_lo = 0, gt_hi = 0, eq_hi = 0;
    int nlo = tb < 63 ? tb : 63;
#pragma unroll 2
    for (int n = 0; n <= nlo; n += 4) {
        u64 accA = 0ull, accB = 0ull;
#pragma unroll
        for (int r = 0; r < DRR; ++r) {
            ulonglong2 w = *(const ulonglong2*)&sKrT[r * TPAD + n];
            u64 q = qr2[r];
            accA = ffma2(q, w.x, accA);
            accB = ffma2(q, w.y, accB);
        }
        accA = fmul2(accA, scale2); accB = fmul2(accB, scale2);
        float sc[4];
        unpack2(accA, sc[0], sc[1]); unpack2(accB, sc[2], sc[3]);
#pragma unroll
        for (int j = 0; j < 4; ++j) {
            if (n + j <= tb) {
                u64 bit = 1ull << (n + j);
                if (sc[j] > tau) gt_lo |= bit;
                else if (sc[j] == tau) eq_lo |= bit;
            }
        }
    }
#pragma unroll 2
    for (int n = 64; n <= tb; n += 4) {
        u64 accA = 0ull, accB = 0ull;
#pragma unroll
        for (int r = 0; r < DRR; ++r) {
            ulonglong2 w = *(const ulonglong2*)&sKrT[r * TPAD + n];
            u64 q = qr2[r];
            accA = ffma2(q, w.x, accA);
            accB = ffma2(q, w.y, accB);
        }
        accA = fmul2(accA, scale2); accB = fmul2(accB, scale2);
        float sc[4];
        unpack2(accA, sc[0], sc[1]); unpack2(accB, sc[2], sc[3]);
#pragma unroll
        for (int j = 0; j < 4; ++j) {
            if (n + j <= tb) {
                u64 bit = 1ull << (n + j - 64);
                if (sc[j] > tau) gt_hi |= bit;
                else if (sc[j] == tau) eq_hi |= bit;
            }
        }
    }
    if (tb < 15) {
        gt_lo |= ((1ull << 15) - (2ull << tb));  // surrogate masked blocks tb+1..14 (> tau)
        eq_lo |= (1ull << 15);                   // surrogate block 15 (tie)
    }

    // tie-fill: lowest-index ==tau bits until 16 selected (jax stable tie rule)
    int need = 16 - __popcll(gt_lo) - __popcll(gt_hi);
    u64 sel_lo = gt_lo, sel_hi = gt_hi;
#pragma unroll 1
    for (int it = 0; it < 16 && need > 0; ++it) {
        if (eq_lo) { u64 bb = eq_lo & (0ull - eq_lo); sel_lo |= bb; eq_lo ^= bb; }
        else if (eq_hi) { u64 bb = eq_hi & (0ull - eq_hi); sel_hi |= bb; eq_hi ^= bb; }
        --need;
    }

    // ---- emit: merge ascending bit-walk with 2 local blocks, keep 16 smallest ----
    int l0 = tb;
    int l1 = tb > 0 ? tb - 1 : 0;  // l1 <= l0
    int li = 0;
    int r[16];
#pragma unroll
    for (int kk = 0; kk < 16; ++kk) {
        bool lo_nz = (sel_lo != 0ull);
        int nb = lo_nz ? (__ffsll((long long)sel_lo) - 1)
                       : (64 + __ffsll((long long)sel_hi) - 1);
        int lc = (li == 0) ? l1 : ((li == 1) ? l0 : 0x7FFFFFFF);
        bool tl = (lc <= nb);
        r[kk] = tl ? lc : nb;
        li += tl ? 1 : 0;
        if (!tl) {
            if (lo_nz) sel_lo &= (sel_lo - 1ull);
            else       sel_hi &= (sel_hi - 1ull);
        }
    }

    // output dtype is float32 (R7 finding)
    float* op = out + ((size_t)((b * TT + t) * HH + h)) * SELK;
    float4* op4 = (float4*)op;
    op4[0] = make_float4((float)r[0],  (float)r[1],  (float)r[2],  (float)r[3]);
    op4[1] = make_float4((float)r[4],  (float)r[5],  (float)r[6],  (float)r[7]);
    op4[2] = make_float4((float)r[8],  (float)r[9],  (float)r[10], (float)r[11]);
    op4[3] = make_float4((float)r[12], (float)r[13], (float)r[14], (float)r[15]);
}

// ---------------- launch: identify inputs by element count (unchanged, passing) ----------------
extern "C" void kernel_launch(void* const* d_in, const int* in_sizes, int n_in,
                              void* d_out, int out_size) {
    const long long SZ_Q  = (long long)BB * TT * HQ * DD;  // 33554432
    const long long SZ_K  = (long long)BB * TT * HH * DD;  // 8388608
    const long long SZ_W  = HH * DD * DRR;                 // 8192
    const long long SZ_LS = HH;                            // 8

    long long unit = 1;
    for (int i = 0; i < n_in; ++i)
        if ((long long)in_sizes[i] == SZ_Q * 4) unit = 4;

    int iQ = -1, iK = -1, iW1 = -1, iW2 = -1, iLS = -1;
    for (int i = 0; i < n_in; ++i) {
        long long s = (long long)in_sizes[i];
        if (s == SZ_Q * unit) iQ = i;
        else if (s == SZ_K * unit) iK = i;
        else if (s == SZ_W * unit) { if (iW1 < 0) iW1 = i; else iW2 = i; }
        else if (s == SZ_LS * unit) iLS = i;
    }
    int iWq = (iQ >= 0 && iK >= 0 && iQ < iK) ? iW1 : iW2;
    int iWk = (iQ >= 0 && iK >= 0 && iQ < iK) ? iW2 : iW1;
    if (iQ < 0) iQ = 0;
    if (iK < 0) iK = 1;
    if (iWq < 0) iWq = 2;
    if (iWk < 0) iWk = 3;
    if (iLS < 0) iLS = 4;

    const float* Q  = (const float*)d_in[iQ];
    const float* K  = (const float*)d_in[iK];
    const float* Wq = (const float*)d_in[iWq];
    const float* Wk = (const float*)d_in[iWk];
    const float* ls = (const float*)d_in[iLS];
    float* out = (float*)d_out;

    dim3 g1(NB, HH, BB);
    kr_kernel<<<g1, 64>>>(K, Wk);

    dim3 g2(TT / (TOK_TILE * 2), HH, BB);  // 32? NO: 64 CTAs of 4 chunks cover 256 chunks
    g2.x = 64;
    router_kernel<<<g2, TOK_TILE>>>(Q, Wq, ls, out);
}